// round 7
// baseline (speedup 1.0000x reference)
#include <cuda_runtime.h>

#define BATCH 4
#define C1    32
#define C2    64
#define MROWS 512
#define NB    128
#define NT    512

// Intermediates (no allocation allowed -> __device__ globals)
__device__ __align__(16) float g_V [MROWS * C2]; // lookup @ Wv       [m][d]
__device__ float g_LT[C2 * MROWS];               // lookup transposed [k][m]
__device__ unsigned g_bar;                       // monotonic grid-barrier ticket

// Software grid barrier: valid because all NB blocks are co-resident
// (128 blocks <= 148 SMs, 512 thr, 16KB smem). Monotonic counter -> safe
// across graph replays with no reset.
__device__ __forceinline__ void gridbar() {
    __threadfence();
    __syncthreads();
    if (threadIdx.x == 0) {
        unsigned ticket = atomicAdd(&g_bar, 1u);
        unsigned target = (ticket / NB + 1u) * NB;
        while (*(volatile unsigned*)&g_bar < target) { }
        __threadfence();
    }
    __syncthreads();
}

__global__ void __launch_bounds__(NT) fused_kernel(
    const float* __restrict__ x,  const float* __restrict__ w1, const float* __restrict__ b1,
    const float* __restrict__ w2, const float* __restrict__ b2,
    const float* __restrict__ lookup, const float* __restrict__ Wv,
    const float* __restrict__ Wo, float* __restrict__ out)
{
    __shared__ __align__(16) float sm[4096];     // 16 KB, phase-overlaid
    float* st  = sm + 3968;    // 128: the 2 token vectors (persists B -> C)
    // Phase B aliases:
    float* sw1 = sm;           // 1536: full conv1 weights
    float* sx  = sm + 1536;    // 600:  x patch [ic][10][20] (18 cols used)
    float* sz1 = sm + 2144;    // 1024: z1 patch [oc][4][8]
    float* zp_ = sm + 3168;    // 512:  conv2 partials
    // Phase C aliases:
    float* ss0 = sm;           // 512
    float* ss1 = sm + 512;     // 512
    float* red = sm + 1024;    // 32
    float* part= sm + 1056;    // 1024
    float* pre = sm + 2080;    // 128
    float* pf  = sm + 2208;    // 512

    int t    = threadIdx.x;
    int blk  = blockIdx.x;
    int lane = t & 31, warp = t >> 5;

    // ============ Phase A: LT transpose + V = lookup@Wv (uniform, tiny) =====
    if (t < 256) sm[t] = lookup[blk * 256 + t];        // this block's 4 rows
    __syncthreads();
    if (t >= 256) {
        int i = t - 256;                               // 0..255
        int k = i >> 2, mi = i & 3;
        g_LT[k * 512 + blk * 4 + mi] = sm[mi * 64 + k];
    } else {
        int d = t & 63;
        const float* row = sm + (t >> 6) * 64;
        float a0 = 0.f, a1 = 0.f, a2 = 0.f, a3 = 0.f;
        #pragma unroll
        for (int k = 0; k < 64; k += 4) {
            a0 += row[k]     * Wv[(k    ) * 64 + d];
            a1 += row[k + 1] * Wv[(k + 1) * 64 + d];
            a2 += row[k + 2] * Wv[(k + 2) * 64 + d];
            a3 += row[k + 3] * Wv[(k + 3) * 64 + d];
        }
        g_V[blk * 256 + t] = (a0 + a1) + (a2 + a3);
    }
    gridbar();   // the ONLY global sync

    // ============ Phase B: conv1(patch) + conv2 for this block's 2 tokens ===
    int b = blk >> 5, p0 = (blk & 31) * 2;             // 2 adjacent pixels
    {
        int oh = p0 >> 3, ow0 = p0 & 7;
        int r0 = 2 * oh - 1,  c0 = 2 * ow0 - 1;        // z1-patch origin
        int xr0 = 2 * r0 - 1, xc0 = 2 * c0 - 1;        // x-patch origin

        // stage w1 (1536) + zero-padded x patch (3 x 10 x 20, 18 used)
        for (int i = t; i < 1536; i += NT) sw1[i] = w1[i];
        for (int i = t; i < 600; i += NT) {
            int ic = i / 200, rem = i % 200;
            int xr = rem / 20, xc = rem % 20;
            float v = 0.f;
            int gr = xr0 + xr, gc = xc0 + xc;
            if (xc < 18 && (unsigned)gr < 32u && (unsigned)gc < 32u)
                v = x[(b * 3 + ic) * 1024 + gr * 32 + gc];
            sx[i] = v;
        }
        __syncthreads();

        // conv1 on the patch: 32 oc x 32 positions (4x8); 2 outputs/thread
        {
            int oc = t >> 4;
            const float* wp = sw1 + oc * 48;
            float bias = b1[oc];
            #pragma unroll
            for (int h = 0; h < 2; h++) {
                int pos = (t & 15) + h * 16;
                int zr = pos >> 3, zc = pos & 7;
                float acc = bias;
                #pragma unroll
                for (int ic = 0; ic < 3; ic++) {
                    const float* xp = sx + ic * 200 + (2 * zr) * 20 + 2 * zc;
                    const float* wq = wp + ic * 16;
                    #pragma unroll
                    for (int u = 0; u < 4; u++) {
                        acc += xp[u * 20]     * wq[u * 4]
                             + xp[u * 20 + 1] * wq[u * 4 + 1]
                             + xp[u * 20 + 2] * wq[u * 4 + 2]
                             + xp[u * 20 + 3] * wq[u * 4 + 3];
                    }
                }
                int gih = r0 + zr, giw = c0 + zc;
                sz1[oc * 32 + pos] =
                    ((unsigned)gih < 16u && (unsigned)giw < 16u) ? fmaxf(acc, 0.f) : 0.f;
            }
        }
        __syncthreads();

        // conv2: pix = t&1, oc = (t>>1)&63, quarter = t>>7 (8 ic each)
        {
            int pix = t & 1, oc = (t >> 1) & 63, qr = t >> 7;
            const float4* W4 = (const float4*)(w2 + (oc * C1 + qr * 8) * 16);
            int cb = 2 * pix;
            float acc = 0.0f;
            #pragma unroll
            for (int ic = 0; ic < 8; ic++) {
                const float* zp = sz1 + (qr * 8 + ic) * 32 + cb;
                float4 wa = W4[ic * 4 + 0], wb = W4[ic * 4 + 1];
                float4 wc = W4[ic * 4 + 2], wd = W4[ic * 4 + 3];
                acc += zp[0]  * wa.x + zp[1]  * wa.y + zp[2]  * wa.z + zp[3]  * wa.w;
                acc += zp[8]  * wb.x + zp[9]  * wb.y + zp[10] * wb.z + zp[11] * wb.w;
                acc += zp[16] * wc.x + zp[17] * wc.y + zp[18] * wc.z + zp[19] * wc.w;
                acc += zp[24] * wd.x + zp[25] * wd.y + zp[26] * wd.z + zp[27] * wd.w;
            }
            zp_[t] = acc;
        }
        __syncthreads();
        if (t < 128) {
            int px = t & 1, o = t >> 1;
            float v = (zp_[t] + zp_[t + 128]) + (zp_[t + 256] + zp_[t + 384]) + b2[o];
            st[px * 64 + o] = fmaxf(v, 0.0f);
        }
        __syncthreads();
    }

    // ============ Phase C: Hopfield retrieve (2 tokens) =====================
    // scores for memory row t (both tokens); coalesced LT; no max subtraction
    // (scores are O(0.3) here, exp is exact-safe; softmax unchanged mathematically)
    float a0 = 0.f, a1 = 0.f, c0s = 0.f, c1s = 0.f;
    #pragma unroll
    for (int k = 0; k < 64; k += 2) {
        float L0 = g_LT[(k    ) * 512 + t];
        float L1 = g_LT[(k + 1) * 512 + t];
        a0  += L0 * st[k];        c0s += L0 * st[64 + k];
        a1  += L1 * st[k + 1];    c1s += L1 * st[64 + k + 1];
    }
    float e0 = __expf((a0 + a1) * 0.125f);     // 1/sqrt(64)
    float e1 = __expf((c0s + c1s) * 0.125f);
    ss0[t] = e0; ss1[t] = e1;

    // block sum (dual)
    float u0 = e0, u1 = e1;
    #pragma unroll
    for (int o = 16; o; o >>= 1) {
        u0 += __shfl_xor_sync(0xffffffffu, u0, o);
        u1 += __shfl_xor_sync(0xffffffffu, u1, o);
    }
    if (lane == 0) { red[warp] = u0; red[16 + warp] = u1; }
    __syncthreads();                 // covers ss writes + red
    float tot0 = red[0], tot1 = red[16];
    #pragma unroll
    for (int i = 1; i < 16; i++) { tot0 += red[i]; tot1 += red[16 + i]; }
    float inv0 = __frcp_rn(tot0), inv1 = __frcp_rn(tot1);

    // p@V dual single-pass: thread (g = t>>6 in 0..7, d = t&63); coalesced V
    {
        int g = t >> 6, d = t & 63;
        const float* Vp = g_V + g * 4096 + d;
        const float* q0 = ss0 + g * 64;
        const float* q1 = ss1 + g * 64;
        float A0 = 0.f, A1 = 0.f, B0 = 0.f, B1 = 0.f;
        #pragma unroll
        for (int m = 0; m < 64; m += 2) {
            float v0 = Vp[m * 64];
            float v1 = Vp[(m + 1) * 64];
            A0 += q0[m] * v0;      B0 += q1[m] * v0;
            A1 += q0[m + 1] * v1;  B1 += q1[m + 1] * v1;
        }
        part[g * 64 + d]       = A0 + A1;
        part[512 + g * 64 + d] = B0 + B1;
    }
    __syncthreads();
    if (t < 128) {
        int j = t >> 6, d = t & 63;
        const float* pp = part + j * 512;
        float s = (pp[d] + pp[64 + d]) + (pp[128 + d] + pp[192 + d])
                + (pp[256 + d] + pp[320 + d]) + (pp[384 + d] + pp[448 + d]);
        pre[j * 64 + d] = s * (j ? inv1 : inv0);
    }
    __syncthreads();

    // @Wo: thread (h4 = t>>7, j = (t>>6)&1, e = t&63); Wo coalesced
    {
        int e = t & 63, j = (t >> 6) & 1, h4 = t >> 7;
        const float* pj = pre + j * 64;
        float acc = 0.f;
        int d0 = h4 * 16;
        #pragma unroll
        for (int d = d0; d < d0 + 16; d++) acc += pj[d] * Wo[d * 64 + e];
        pf[t] = acc;
    }
    __syncthreads();
    if (t < 128) {
        int j = t >> 6, e = t & 63;
        out[b * 4096 + e * 64 + p0 + j] =
            (pf[t] + pf[t + 128]) + (pf[t + 256] + pf[t + 384]);
    }
}

// ---------------------------------------------------------------------------
extern "C" void kernel_launch(void* const* d_in, const int* in_sizes, int n_in,
                              void* d_out, int out_size) {
    const float* x       = (const float*)d_in[0];
    const float* conv1_w = (const float*)d_in[1];
    const float* conv1_b = (const float*)d_in[2];
    const float* conv2_w = (const float*)d_in[3];
    const float* conv2_b = (const float*)d_in[4];
    const float* lookup  = (const float*)d_in[5];
    const float* Wv      = (const float*)d_in[6];
    const float* Wo      = (const float*)d_in[7];
    float* out = (float*)d_out;

    fused_kernel<<<NB, NT>>>(x, conv1_w, conv1_b, conv2_w, conv2_b,
                             lookup, Wv, Wo, out);
}

// round 8
// speedup vs baseline: 1.4422x; 1.4422x over previous
#include <cuda_runtime.h>

#define BATCH 4
#define C1    32
#define C2    64
#define MROWS 512
#define NB    128
#define NT    512

// Intermediates (no allocation allowed -> __device__ globals)
__device__ float g_z1[BATCH * C1 * 256];          // conv1 out: [b][ic][16x16]
__device__ __align__(16) float g_V [MROWS * C2];  // lookup @ Wv       [m][d]
__device__ float g_LT [C2 * MROWS];               // lookup transposed [k][m]
__device__ float g_w2T[512 * C2];                 // conv2 w transposed [k][oc]
__device__ unsigned g_bar;                        // monotonic grid-barrier ticket

// Software grid barrier: valid because all NB blocks are co-resident
// (128 blocks <= 148 SMs, 512 thr, 13KB smem). Monotonic counter -> safe
// across graph replays with no reset.
__device__ __forceinline__ void gridbar() {
    __threadfence();
    __syncthreads();
    if (threadIdx.x == 0) {
        unsigned ticket = atomicAdd(&g_bar, 1u);
        unsigned target = (ticket / NB + 1u) * NB;
        while (*(volatile unsigned*)&g_bar < target) { }
        __threadfence();
    }
    __syncthreads();
}

__global__ void __launch_bounds__(NT, 1) fused_kernel(
    const float* __restrict__ x,  const float* __restrict__ w1, const float* __restrict__ b1,
    const float* __restrict__ w2, const float* __restrict__ b2,
    const float* __restrict__ lookup, const float* __restrict__ Wv,
    const float* __restrict__ Wo, float* __restrict__ out)
{
    __shared__ __align__(16) float sm[3200];   // 12.8 KB, phase-overlaid
    float* st  = sm;           // 128: the 2 token vectors (persists B -> C)
    // Phase B aliases (start at 128, st untouched):
    float* sz1 = sm + 128;     // 1024: z1 patch [ic][4][8pad]
    float* z1v = sm + 1152;    // 1024: gathered conv2 input vecs [pix][512]
    float* zpA = sm + 2176;    // 512:  conv2 partials pixel0
    float* zpB = sm + 2688;    // 512:  conv2 partials pixel1
    // Phase C aliases (start at 128, st untouched):
    float* ss0 = sm + 128;     // 512
    float* ss1 = sm + 640;     // 512
    float* red = sm + 1152;    // 32
    float* part= sm + 1184;    // 1024
    float* pre = sm + 2208;    // 128
    float* pf  = sm + 2336;    // 512

    int t    = threadIdx.x;
    int blk  = blockIdx.x;
    int lane = t & 31, warp = t >> 5;

    // ============ Phase A: conv1 (t<256) || LT + vmat + w2T (t>=256) ========
    if (t < 48)   sm[t] = w1[(blk & 31) * 48 + t];
    if (t >= 256) sm[64 + (t - 256)] = lookup[blk * 256 + (t - 256)];
    __syncthreads();

    if (t < 256) {
        // conv1: block -> (b, oc); thread -> output pixel. k4 s2 p1 relu.
        int b = blk >> 5, oc = blk & 31;
        int oh = t >> 4, ow = t & 15;
        int iw0 = ow * 2 - 1;
        float acc = b1[oc];
        #pragma unroll
        for (int ic = 0; ic < 3; ic++) {
            const float* xp  = x + (b * 3 + ic) * 1024;
            const float* swp = sm + ic * 16;
            #pragma unroll
            for (int kh = 0; kh < 4; kh++) {
                int ih = oh * 2 - 1 + kh;
                if ((unsigned)ih < 32u) {
                    const float* xr = xp + ih * 32;
                    if (iw0 >= 0)  acc += xr[iw0]     * swp[kh * 4];
                    acc += xr[iw0 + 1] * swp[kh * 4 + 1];
                    acc += xr[iw0 + 2] * swp[kh * 4 + 2];
                    if (iw0 < 29)  acc += xr[iw0 + 3] * swp[kh * 4 + 3];
                }
            }
        }
        g_z1[(b * C1 + oc) * 256 + t] = fmaxf(acc, 0.0f);
    } else {
        int i = t - 256;                              // 0..255
        // lookup transpose: g_LT[k][4*blk+mi] = row[mi][k]
        {
            int k = i >> 2, mi = i & 3;
            g_LT[k * 512 + blk * 4 + mi] = sm[64 + mi * 64 + k];
        }
        // w2 transpose: coalesced read, scattered write (fire-and-forget)
        {
            int j = blk * 256 + i;                    // 0..32767
            g_w2T[(j & 511) * 64 + (j >> 9)] = w2[j];
        }
        // vmat: V[4blk+r][d] = row_r . Wv[:,d]
        int d = i & 63;
        const float* row = sm + 64 + (i >> 6) * 64;
        float a0 = 0.f, a1 = 0.f, a2 = 0.f, a3 = 0.f;
        #pragma unroll
        for (int k = 0; k < 64; k += 4) {
            a0 += row[k]     * Wv[(k    ) * 64 + d];
            a1 += row[k + 1] * Wv[(k + 1) * 64 + d];
            a2 += row[k + 2] * Wv[(k + 2) * 64 + d];
            a3 += row[k + 3] * Wv[(k + 3) * 64 + d];
        }
        g_V[blk * 256 + i] = (a0 + a1) + (a2 + a3);
    }
    gridbar();   // the ONLY global sync

    // ============ Phase B: conv2 for this block's 2 tokens (coalesced GEMV) =
    int b = blk >> 5, p0 = (blk & 31) * 2;    // 2 adjacent pixels, same row
    {
        int oh = p0 >> 3, ow0 = p0 & 7;
        int r0 = 2 * oh - 1, c0 = 2 * ow0 - 1;

        // zero-padded z1 patch: 32 ic x 4 rows x 6 cols (stored 8-padded)
        for (int i = t; i < 1024; i += NT) {
            int ic = i >> 5, e = i & 31;
            int kh = e >> 3, kc = e & 7;
            float v = 0.0f;
            if (kc < 6) {
                int ih = r0 + kh, iw = c0 + kc;
                if ((unsigned)ih < 16u && (unsigned)iw < 16u)
                    v = g_z1[(b * C1 + ic) * 256 + ih * 16 + iw];
            }
            sz1[i] = v;
        }
        __syncthreads();

        // gather per-pixel input vectors: z1v[pix][k], k = ic*16 + kh*4 + kw
        for (int i = t; i < 1024; i += NT) {
            int pix = i >> 9, k = i & 511;
            int ic = k >> 4, kh = (k >> 2) & 3, kw = k & 3;
            z1v[i] = sz1[ic * 32 + kh * 8 + kw + 2 * pix];
        }
        __syncthreads();

        // GEMV: thread (oc = t&63, qr = t>>6 of 8 k-groups); 1 line/warp loads
        {
            int oc = t & 63, qr = t >> 6;
            const float* wt = g_w2T + (qr * 64) * 64 + oc;
            const float* v0 = z1v + qr * 64;
            const float* v1 = z1v + 512 + qr * 64;
            float a0 = 0.f, a1 = 0.f, b0 = 0.f, b1a = 0.f;
            #pragma unroll
            for (int j = 0; j < 64; j += 2) {
                float wA = wt[j * 64];
                float wB = wt[(j + 1) * 64];
                a0  += wA * v0[j];      b0  += wA * v1[j];
                a1  += wB * v0[j + 1];  b1a += wB * v1[j + 1];
            }
            zpA[t] = a0 + a1;
            zpB[t] = b0 + b1a;
        }
        __syncthreads();
        if (t < 128) {
            int pix = t >> 6, o = t & 63;
            const float* zp = pix ? zpB : zpA;
            float s = (zp[o] + zp[64 + o]) + (zp[128 + o] + zp[192 + o])
                    + (zp[256 + o] + zp[320 + o]) + (zp[384 + o] + zp[448 + o]);
            st[pix * 64 + o] = fmaxf(s + b2[o], 0.0f);
        }
        __syncthreads();
    }

    // ============ Phase C: Hopfield retrieve (2 tokens) =====================
    // scores for memory row t (both tokens); coalesced LT; no max subtraction
    // (scores are O(0.3), exp exact-safe; softmax mathematically unchanged)
    float a0 = 0.f, a1 = 0.f, c0s = 0.f, c1s = 0.f;
    #pragma unroll
    for (int k = 0; k < 64; k += 2) {
        float L0 = g_LT[(k    ) * 512 + t];
        float L1 = g_LT[(k + 1) * 512 + t];
        a0  += L0 * st[k];        c0s += L0 * st[64 + k];
        a1  += L1 * st[k + 1];    c1s += L1 * st[64 + k + 1];
    }
    float e0 = __expf((a0 + a1) * 0.125f);     // 1/sqrt(64)
    float e1 = __expf((c0s + c1s) * 0.125f);
    ss0[t] = e0; ss1[t] = e1;

    // block sum (dual)
    float u0 = e0, u1 = e1;
    #pragma unroll
    for (int o = 16; o; o >>= 1) {
        u0 += __shfl_xor_sync(0xffffffffu, u0, o);
        u1 += __shfl_xor_sync(0xffffffffu, u1, o);
    }
    if (lane == 0) { red[warp] = u0; red[16 + warp] = u1; }
    __syncthreads();                 // covers ss writes + red
    float tot0 = red[0], tot1 = red[16];
    #pragma unroll
    for (int i = 1; i < 16; i++) { tot0 += red[i]; tot1 += red[16 + i]; }
    float inv0 = __frcp_rn(tot0), inv1 = __frcp_rn(tot1);

    // p@V dual single-pass: thread (g = t>>6 in 0..7, d = t&63); coalesced V
    {
        int g = t >> 6, d = t & 63;
        const float* Vp = g_V + g * 4096 + d;
        const float* q0 = ss0 + g * 64;
        const float* q1 = ss1 + g * 64;
        float A0 = 0.f, A1 = 0.f, B0 = 0.f, B1 = 0.f;
        #pragma unroll
        for (int m = 0; m < 64; m += 2) {
            float v0 = Vp[m * 64];
            float v1 = Vp[(m + 1) * 64];
            A0 += q0[m] * v0;      B0 += q1[m] * v0;
            A1 += q0[m + 1] * v1;  B1 += q1[m + 1] * v1;
        }
        part[g * 64 + d]       = A0 + A1;
        part[512 + g * 64 + d] = B0 + B1;
    }
    __syncthreads();
    if (t < 128) {
        int j = t >> 6, d = t & 63;
        const float* pp = part + j * 512;
        float s = (pp[d] + pp[64 + d]) + (pp[128 + d] + pp[192 + d])
                + (pp[256 + d] + pp[320 + d]) + (pp[384 + d] + pp[448 + d]);
        pre[j * 64 + d] = s * (j ? inv1 : inv0);
    }
    __syncthreads();

    // @Wo: thread (h4 = t>>7, j = (t>>6)&1, e = t&63); Wo coalesced
    {
        int e = t & 63, j = (t >> 6) & 1, h4 = t >> 7;
        const float* pj = pre + j * 64;
        float acc = 0.f;
        int d0 = h4 * 16;
        #pragma unroll
        for (int d = d0; d < d0 + 16; d++) acc += pj[d] * Wo[d * 64 + e];
        pf[t] = acc;
    }
    __syncthreads();
    if (t < 128) {
        int j = t >> 6, e = t & 63;
        out[b * 4096 + e * 64 + p0 + j] =
            (pf[t] + pf[t + 128]) + (pf[t + 256] + pf[t + 384]);
    }
}

// ---------------------------------------------------------------------------
extern "C" void kernel_launch(void* const* d_in, const int* in_sizes, int n_in,
                              void* d_out, int out_size) {
    const float* x       = (const float*)d_in[0];
    const float* conv1_w = (const float*)d_in[1];
    const float* conv1_b = (const float*)d_in[2];
    const float* conv2_w = (const float*)d_in[3];
    const float* conv2_b = (const float*)d_in[4];
    const float* lookup  = (const float*)d_in[5];
    const float* Wv      = (const float*)d_in[6];
    const float* Wo      = (const float*)d_in[7];
    float* out = (float*)d_out;

    fused_kernel<<<NB, NT>>>(x, conv1_w, conv1_b, conv2_w, conv2_b,
                             lookup, Wv, Wo, out);
}